// round 14
// baseline (speedup 1.0000x reference)
#include <cuda_runtime.h>
#include <cuda_fp16.h>
#include <cstdint>
#include <cstddef>

#define B_ 32
#define T_ 2048
#define H_ 1024
#define E_ 1024

// ---------------- device scratch (no allocations allowed) ----------------
__device__ __half g_W2h[H_ * E_];            // W2 fp16, [k][e]
__device__ float  g_dec_proj[B_ * H_];       // [b][k]
__device__ float  g_spart[8 * B_ * T_];      // per-N-tile score partials
__device__ float  g_scores[B_ * T_];         // reduced scores
__device__ float  g_cpart[8 * B_ * E_];      // per-t-split context partials

// ---------------- helpers ----------------
__device__ __forceinline__ uint32_t smem_u32(const void* p) {
    uint32_t a;
    asm("{ .reg .u64 t; cvta.to.shared.u64 t, %1; cvt.u32.u64 %0, t; }" : "=r"(a) : "l"(p));
    return a;
}
__device__ __forceinline__ void cp16(void* s, const void* g) {
    unsigned sa = smem_u32(s);
    asm volatile("cp.async.cg.shared.global [%0], [%1], 16;\n" :: "r"(sa), "l"(g));
}
__device__ __forceinline__ void ldm_x4(unsigned& r0, unsigned& r1, unsigned& r2, unsigned& r3,
                                       const void* p) {
    unsigned addr = smem_u32(p);
    asm volatile("ldmatrix.sync.aligned.m8n8.x4.shared.b16 {%0,%1,%2,%3}, [%4];\n"
                 : "=r"(r0), "=r"(r1), "=r"(r2), "=r"(r3) : "r"(addr));
}
__device__ __forceinline__ void mma16816(float* c, const unsigned* a, const unsigned* b) {
    asm volatile("mma.sync.aligned.m16n8k16.row.col.f32.f16.f16.f32 "
                 "{%0,%1,%2,%3}, {%4,%5,%6,%7}, {%8,%9}, {%0,%1,%2,%3};\n"
                 : "+f"(c[0]), "+f"(c[1]), "+f"(c[2]), "+f"(c[3])
                 : "r"(a[0]), "r"(a[1]), "r"(a[2]), "r"(a[3]), "r"(b[0]), "r"(b[1]));
}

// ---------------- kernel 1: W2 fp32 -> fp16 ----------------
__global__ void k_w2_convert(const float* __restrict__ W2) {
    int i = (blockIdx.x * blockDim.x + threadIdx.x) * 4;
    float4 f = *reinterpret_cast<const float4*>(W2 + i);
    *reinterpret_cast<__half2*>(&g_W2h[i])     = __floats2half2_rn(f.x, f.y);
    *reinterpret_cast<__half2*>(&g_W2h[i + 2]) = __floats2half2_rn(f.z, f.w);
}

// ---------------- kernel 2: dec_proj[b,k] = sum_h dec[b,h] * W1[k,h] (fp32) ----------------
__global__ void k_dec_proj(const float* __restrict__ dec, const float* __restrict__ W1) {
    __shared__ float sdec[32 * 65];
    __shared__ float sW1[16 * 65];
    const int n0 = blockIdx.x * 16;
    const int tid = threadIdx.x;
    const int nl = tid & 15, q = tid >> 4;
    float a0 = 0.f, a1 = 0.f;
    for (int h0 = 0; h0 < H_; h0 += 64) {
        __syncthreads();
        #pragma unroll
        for (int j = 0; j < 8; j++) {
            int idx = tid + j * 256;
            int bb = idx >> 6, hh = idx & 63;
            sdec[bb * 65 + hh] = dec[bb * H_ + h0 + hh];
        }
        #pragma unroll
        for (int j = 0; j < 4; j++) {
            int idx = tid + j * 256;
            int nn = idx >> 6, hh = idx & 63;
            sW1[nn * 65 + hh] = W1[(size_t)(n0 + nn) * H_ + h0 + hh];
        }
        __syncthreads();
        #pragma unroll
        for (int h = 0; h < 64; h++) {
            float wv = sW1[nl * 65 + h];
            a0 += sdec[q * 65 + h] * wv;
            a1 += sdec[(q + 16) * 65 + h] * wv;
        }
    }
    g_dec_proj[q * H_ + n0 + nl] = a0;
    g_dec_proj[(q + 16) * H_ + n0 + nl] = a1;
}

// ---------------- kernel 3: fused scores GEMM (R6 schedule, measured-best) ----------------
#define BM 128
#define BN 128
#define BK 32
#define AST 40   // smem row stride in halfs (80B: conflict-free LDSM phases)
#define BST 40
#define NIT (E_ / BK)

__global__ void __launch_bounds__(256, 2)
k_main(const float* __restrict__ enc, const float* __restrict__ vvec) {
    __shared__ __half As[2][BM * AST];
    __shared__ __half Bs[2][BN * BST];
    __shared__ float  sred[2 * BM];

    const int mtile = blockIdx.x >> 3;
    const int nt    = blockIdx.x & 7;
    const int row0  = mtile * BM;
    const int n0    = nt * BN;
    const int tid   = threadIdx.x;
    const int w = tid >> 5, l = tid & 31;
    const int wm = w >> 1, wn = w & 1;
    const int g = l >> 2, tg = l & 3;

    // this thread's two A chunks: chunk c = tid + j*256 -> row c>>2, col (c&3)*8
    const int ar0 = (tid + 0)   >> 2, ac0 = ((tid + 0)   & 3) * 8;
    const int ar1 = (tid + 256) >> 2, ac1 = ((tid + 256) & 3) * 8;

    float4 apre[4];
    auto ldgA = [&](int kc) {
        const float4* p0 = reinterpret_cast<const float4*>(enc + (size_t)(row0 + ar0) * E_ + kc + ac0);
        const float4* p1 = reinterpret_cast<const float4*>(enc + (size_t)(row0 + ar1) * E_ + kc + ac1);
        apre[0] = p0[0]; apre[1] = p0[1];
        apre[2] = p1[0]; apre[3] = p1[1];
    };
    auto stsA = [&](int s) {
        __half2 h[4];
        h[0] = __floats2half2_rn(apre[0].x, apre[0].y);
        h[1] = __floats2half2_rn(apre[0].z, apre[0].w);
        h[2] = __floats2half2_rn(apre[1].x, apre[1].y);
        h[3] = __floats2half2_rn(apre[1].z, apre[1].w);
        *reinterpret_cast<uint4*>(&As[s][ar0 * AST + ac0]) = *reinterpret_cast<uint4*>(h);
        h[0] = __floats2half2_rn(apre[2].x, apre[2].y);
        h[1] = __floats2half2_rn(apre[2].z, apre[2].w);
        h[2] = __floats2half2_rn(apre[3].x, apre[3].y);
        h[3] = __floats2half2_rn(apre[3].z, apre[3].w);
        *reinterpret_cast<uint4*>(&As[s][ar1 * AST + ac1]) = *reinterpret_cast<uint4*>(h);
    };
    auto loadB = [&](int s, int kc) {
        #pragma unroll
        for (int j = 0; j < 2; j++) {
            int c = tid + j * 256;
            int r = c >> 2, cf = c & 3;
            cp16(&Bs[s][r * BST + cf * 8], g_W2h + (size_t)(n0 + r) * E_ + kc + cf * 8);
        }
        asm volatile("cp.async.commit_group;\n" ::: "memory");
    };

    float acc[2][8][4] = {};

    // preamble: stage 0
    ldgA(0);
    loadB(0, 0);
    stsA(0);

    // ldmatrix lane addressing
    const int a_row = l & 15, a_k8 = (l >> 4) * 8;
    const int bj = l >> 3, br = l & 7;
    const int b_rowadd = ((bj >> 1) * 8) + br, b_k8 = (bj & 1) * 8;

    #pragma unroll 1
    for (int it = 0; it < NIT; ++it) {
        if (it + 1 < NIT) {
            ldgA((it + 1) * BK);                 // A prefetch into regs
            loadB((it + 1) & 1, (it + 1) * BK);  // B prefetch into smem
            asm volatile("cp.async.wait_group 1;\n" ::: "memory");
        } else {
            asm volatile("cp.async.wait_group 0;\n" ::: "memory");
        }
        __syncthreads();   // As/Bs stage (it&1) fully visible; prior reads of other buf done
        const __half* Ab = As[it & 1];
        const __half* Bb = Bs[it & 1];

        #pragma unroll
        for (int kk = 0; kk < 2; kk++) {
            const int kc = kk * 16;
            unsigned a[2][4];
            #pragma unroll
            for (int mb = 0; mb < 2; mb++) {
                int mbase = wm * 32 + mb * 16;
                ldm_x4(a[mb][0], a[mb][1], a[mb][2], a[mb][3],
                       Ab + (mbase + a_row) * AST + kc + a_k8);
            }
            unsigned bf[8][2];
            #pragma unroll
            for (int nbp = 0; nbp < 4; nbp++) {
                int nbase = wn * 64 + nbp * 16;
                unsigned r0, r1, r2, r3;
                ldm_x4(r0, r1, r2, r3, Bb + (nbase + b_rowadd) * BST + kc + b_k8);
                bf[nbp * 2][0] = r0;     bf[nbp * 2][1] = r1;
                bf[nbp * 2 + 1][0] = r2; bf[nbp * 2 + 1][1] = r3;
            }
            #pragma unroll
            for (int mb = 0; mb < 2; mb++)
                #pragma unroll
                for (int nb = 0; nb < 8; nb++)
                    mma16816(acc[mb][nb], a[mb], bf[nb]);
        }
        if (it + 1 < NIT) stsA((it + 1) & 1);   // safe: other buffer; ordered by next barrier
        __syncthreads();
    }

    // ---- fused epilogue: tanh + v-dot, reduce over this CTA's 128 k's ----
    const int b = row0 / T_;
    float dp0[8], dp1[8], v0r[8], v1r[8];
    #pragma unroll
    for (int nb = 0; nb < 8; nb++) {
        int col = n0 + wn * 64 + nb * 8 + 2 * tg;
        dp0[nb] = g_dec_proj[b * H_ + col];
        dp1[nb] = g_dec_proj[b * H_ + col + 1];
        v0r[nb] = vvec[col];
        v1r[nb] = vvec[col + 1];
    }
    float rs[4] = {0.f, 0.f, 0.f, 0.f};
    #pragma unroll
    for (int mb = 0; mb < 2; mb++)
        #pragma unroll
        for (int nb = 0; nb < 8; nb++) {
            rs[mb * 2 + 0] += v0r[nb] * tanhf(acc[mb][nb][0] + dp0[nb])
                            + v1r[nb] * tanhf(acc[mb][nb][1] + dp1[nb]);
            rs[mb * 2 + 1] += v0r[nb] * tanhf(acc[mb][nb][2] + dp0[nb])
                            + v1r[nb] * tanhf(acc[mb][nb][3] + dp1[nb]);
        }
    #pragma unroll
    for (int i = 0; i < 4; i++) {
        rs[i] += __shfl_xor_sync(0xffffffffu, rs[i], 1);
        rs[i] += __shfl_xor_sync(0xffffffffu, rs[i], 2);
    }
    if (tg == 0) {
        #pragma unroll
        for (int i = 0; i < 4; i++) {
            int r = wm * 32 + (i >> 1) * 16 + (i & 1) * 8 + g;
            sred[wn * BM + r] = rs[i];
        }
    }
    __syncthreads();
    if (tid < BM)
        g_spart[(size_t)nt * (B_ * T_) + row0 + tid] = sred[tid] + sred[BM + tid];
}

// ---------------- kernel 3b: wide pre-reduce of the 8 score partials ----------------
__global__ void k_sred() {
    int i = blockIdx.x * 256 + threadIdx.x;
    float x = 0.f;
    #pragma unroll
    for (int p = 0; p < 8; p++) x += g_spart[(size_t)p * (B_ * T_) + i];
    g_scores[i] = x;
}

// ---------------- kernel 4: softmax over T per batch ----------------
__global__ void k_softmax(float* __restrict__ attn) {
    __shared__ float s[T_];
    __shared__ float red[8];
    const int b = blockIdx.x, tid = threadIdx.x;
    const int wid = tid >> 5, lane = tid & 31;
    float lmax = -1e30f;
    #pragma unroll
    for (int j = 0; j < 8; j++) {
        int t = tid + j * 256;
        float x = g_scores[b * T_ + t];
        s[t] = x;
        lmax = fmaxf(lmax, x);
    }
    #pragma unroll
    for (int o = 16; o > 0; o >>= 1) lmax = fmaxf(lmax, __shfl_xor_sync(~0u, lmax, o));
    if (lane == 0) red[wid] = lmax;
    __syncthreads();
    float smax = red[0];
    #pragma unroll
    for (int k = 1; k < 8; k++) smax = fmaxf(smax, red[k]);
    float lsum = 0.f;
    #pragma unroll
    for (int j = 0; j < 8; j++) lsum += expf(s[tid + j * 256] - smax);
    #pragma unroll
    for (int o = 16; o > 0; o >>= 1) lsum += __shfl_xor_sync(~0u, lsum, o);
    __syncthreads();
    if (lane == 0) red[wid] = lsum;
    __syncthreads();
    float ssum = 0.f;
    #pragma unroll
    for (int k = 0; k < 8; k++) ssum += red[k];
    float inv = 1.f / ssum;
    #pragma unroll
    for (int j = 0; j < 8; j++) {
        int t = tid + j * 256;
        attn[b * T_ + t] = expf(s[t] - smax) * inv;
    }
}

// ---------------- kernel 5: context partials (float4, deterministic t-split) ----------------
__global__ void k_ctx_part(const float* __restrict__ enc, const float* __restrict__ attn) {
    __shared__ float sA[256];
    const int b = blockIdx.x, ts = blockIdx.y;
    const int e4 = threadIdx.x * 4;                // this thread's 4 e-values
    const int t0 = ts * 256;
    sA[threadIdx.x] = attn[b * T_ + t0 + threadIdx.x];
    __syncthreads();
    const float4* base = reinterpret_cast<const float4*>(
        enc + ((size_t)(b * T_ + t0)) * E_ + e4);
    float ax = 0.f, ay = 0.f, az = 0.f, aw = 0.f;
    #pragma unroll 8
    for (int j = 0; j < 256; j++) {
        float4 v = base[(size_t)j * (E_ / 4)];
        float wgt = sA[j];
        ax += wgt * v.x;
        ay += wgt * v.y;
        az += wgt * v.z;
        aw += wgt * v.w;
    }
    float4* dst = reinterpret_cast<float4*>(&g_cpart[((size_t)ts * B_ + b) * E_ + e4]);
    *dst = make_float4(ax, ay, az, aw);
}

// ---------------- kernel 6: context final sum ----------------
__global__ void k_ctx_sum(float* __restrict__ out) {
    int i = blockIdx.x * 256 + threadIdx.x;
    float x = 0.f;
    #pragma unroll
    for (int ts = 0; ts < 8; ts++) x += g_cpart[(size_t)ts * (B_ * E_) + i];
    out[i] = x;
}

// ---------------- launch ----------------
extern "C" void kernel_launch(void* const* d_in, const int* in_sizes, int n_in,
                              void* d_out, int out_size) {
    const float* dec = (const float*)d_in[0];   // [B,H]
    const float* enc = (const float*)d_in[1];   // [B,T,E]
    const float* W1  = (const float*)d_in[2];   // [H,H]
    const float* W2  = (const float*)d_in[3];   // [H,E]
    const float* v   = (const float*)d_in[4];   // [H]
    float* out = (float*)d_out;                 // context [B,E] then attn [B,T]

    k_w2_convert<<<(H_ * E_) / 1024, 256>>>(W2);
    k_dec_proj<<<H_ / 16, 256>>>(dec, W1);
    k_main<<<(B_ * T_ / BM) * 8, 256>>>(enc, v);
    k_sred<<<(B_ * T_) / 256, 256>>>();
    k_softmax<<<B_, 256>>>(out + B_ * E_);
    dim3 gctx(B_, 8);
    k_ctx_part<<<gctx, 256>>>(enc, out + B_ * E_);
    k_ctx_sum<<<(B_ * E_) / 256, 256>>>(out);
}

// round 16
// speedup vs baseline: 1.0252x; 1.0252x over previous
#include <cuda_runtime.h>
#include <cuda_fp16.h>
#include <cstdint>
#include <cstddef>

#define B_ 32
#define T_ 2048
#define H_ 1024
#define E_ 1024

// ---------------- device scratch (no allocations allowed) ----------------
__device__ __half g_W2h[H_ * E_];            // W2 fp16, [k][e]
__device__ float  g_dec_proj[B_ * H_];       // [b][k]
__device__ float  g_spart[8 * B_ * T_];      // per-N-tile score partials
__device__ float  g_cpart[8 * B_ * E_];      // per-t-split context partials

// ---------------- helpers ----------------
__device__ __forceinline__ uint32_t smem_u32(const void* p) {
    uint32_t a;
    asm("{ .reg .u64 t; cvta.to.shared.u64 t, %1; cvt.u32.u64 %0, t; }" : "=r"(a) : "l"(p));
    return a;
}
__device__ __forceinline__ void cp16(void* s, const void* g) {
    unsigned sa = smem_u32(s);
    asm volatile("cp.async.cg.shared.global [%0], [%1], 16;\n" :: "r"(sa), "l"(g));
}
__device__ __forceinline__ void ldm_x4(unsigned& r0, unsigned& r1, unsigned& r2, unsigned& r3,
                                       const void* p) {
    unsigned addr = smem_u32(p);
    asm volatile("ldmatrix.sync.aligned.m8n8.x4.shared.b16 {%0,%1,%2,%3}, [%4];\n"
                 : "=r"(r0), "=r"(r1), "=r"(r2), "=r"(r3) : "r"(addr));
}
__device__ __forceinline__ void mma16816(float* c, const unsigned* a, const unsigned* b) {
    asm volatile("mma.sync.aligned.m16n8k16.row.col.f32.f16.f16.f32 "
                 "{%0,%1,%2,%3}, {%4,%5,%6,%7}, {%8,%9}, {%0,%1,%2,%3};\n"
                 : "+f"(c[0]), "+f"(c[1]), "+f"(c[2]), "+f"(c[3])
                 : "r"(a[0]), "r"(a[1]), "r"(a[2]), "r"(a[3]), "r"(b[0]), "r"(b[1]));
}

// ---------------- kernel 1: W2 fp32 -> fp16 ----------------
__global__ void k_w2_convert(const float* __restrict__ W2) {
    int i = (blockIdx.x * blockDim.x + threadIdx.x) * 4;
    float4 f = *reinterpret_cast<const float4*>(W2 + i);
    *reinterpret_cast<__half2*>(&g_W2h[i])     = __floats2half2_rn(f.x, f.y);
    *reinterpret_cast<__half2*>(&g_W2h[i + 2]) = __floats2half2_rn(f.z, f.w);
}

// ---------------- kernel 2: dec_proj[b,k] = sum_h dec[b,h] * W1[k,h] (fp32) ----------------
__global__ void k_dec_proj(const float* __restrict__ dec, const float* __restrict__ W1) {
    __shared__ float sdec[32 * 65];
    __shared__ float sW1[16 * 65];
    const int n0 = blockIdx.x * 16;
    const int tid = threadIdx.x;
    const int nl = tid & 15, q = tid >> 4;
    float a0 = 0.f, a1 = 0.f;
    for (int h0 = 0; h0 < H_; h0 += 64) {
        __syncthreads();
        #pragma unroll
        for (int j = 0; j < 8; j++) {
            int idx = tid + j * 256;
            int bb = idx >> 6, hh = idx & 63;
            sdec[bb * 65 + hh] = dec[bb * H_ + h0 + hh];
        }
        #pragma unroll
        for (int j = 0; j < 4; j++) {
            int idx = tid + j * 256;
            int nn = idx >> 6, hh = idx & 63;
            sW1[nn * 65 + hh] = W1[(size_t)(n0 + nn) * H_ + h0 + hh];
        }
        __syncthreads();
        #pragma unroll
        for (int h = 0; h < 64; h++) {
            float wv = sW1[nl * 65 + h];
            a0 += sdec[q * 65 + h] * wv;
            a1 += sdec[(q + 16) * 65 + h] * wv;
        }
    }
    g_dec_proj[q * H_ + n0 + nl] = a0;
    g_dec_proj[(q + 16) * H_ + n0 + nl] = a1;
}

// ---------------- kernel 3: fused scores GEMM (R6 schedule, measured-best) ----------------
#define BM 128
#define BN 128
#define BK 32
#define AST 40   // smem row stride in halfs (80B: conflict-free LDSM phases)
#define BST 40
#define NIT (E_ / BK)

__global__ void __launch_bounds__(256, 2)
k_main(const float* __restrict__ enc, const float* __restrict__ vvec) {
    __shared__ __half As[2][BM * AST];
    __shared__ __half Bs[2][BN * BST];
    __shared__ float  sred[2 * BM];

    const int mtile = blockIdx.x >> 3;
    const int nt    = blockIdx.x & 7;
    const int row0  = mtile * BM;
    const int n0    = nt * BN;
    const int tid   = threadIdx.x;
    const int w = tid >> 5, l = tid & 31;
    const int wm = w >> 1, wn = w & 1;
    const int g = l >> 2, tg = l & 3;

    // this thread's two A chunks: chunk c = tid + j*256 -> row c>>2, col (c&3)*8
    const int ar0 = (tid + 0)   >> 2, ac0 = ((tid + 0)   & 3) * 8;
    const int ar1 = (tid + 256) >> 2, ac1 = ((tid + 256) & 3) * 8;

    float4 apre[4];
    auto ldgA = [&](int kc) {
        const float4* p0 = reinterpret_cast<const float4*>(enc + (size_t)(row0 + ar0) * E_ + kc + ac0);
        const float4* p1 = reinterpret_cast<const float4*>(enc + (size_t)(row0 + ar1) * E_ + kc + ac1);
        apre[0] = p0[0]; apre[1] = p0[1];
        apre[2] = p1[0]; apre[3] = p1[1];
    };
    auto stsA = [&](int s) {
        __half2 h[4];
        h[0] = __floats2half2_rn(apre[0].x, apre[0].y);
        h[1] = __floats2half2_rn(apre[0].z, apre[0].w);
        h[2] = __floats2half2_rn(apre[1].x, apre[1].y);
        h[3] = __floats2half2_rn(apre[1].z, apre[1].w);
        *reinterpret_cast<uint4*>(&As[s][ar0 * AST + ac0]) = *reinterpret_cast<uint4*>(h);
        h[0] = __floats2half2_rn(apre[2].x, apre[2].y);
        h[1] = __floats2half2_rn(apre[2].z, apre[2].w);
        h[2] = __floats2half2_rn(apre[3].x, apre[3].y);
        h[3] = __floats2half2_rn(apre[3].z, apre[3].w);
        *reinterpret_cast<uint4*>(&As[s][ar1 * AST + ac1]) = *reinterpret_cast<uint4*>(h);
    };
    auto loadB = [&](int s, int kc) {
        #pragma unroll
        for (int j = 0; j < 2; j++) {
            int c = tid + j * 256;
            int r = c >> 2, cf = c & 3;
            cp16(&Bs[s][r * BST + cf * 8], g_W2h + (size_t)(n0 + r) * E_ + kc + cf * 8);
        }
        asm volatile("cp.async.commit_group;\n" ::: "memory");
    };

    float acc[2][8][4] = {};

    // preamble: stage 0
    ldgA(0);
    loadB(0, 0);
    stsA(0);

    // ldmatrix lane addressing
    const int a_row = l & 15, a_k8 = (l >> 4) * 8;
    const int bj = l >> 3, br = l & 7;
    const int b_rowadd = ((bj >> 1) * 8) + br, b_k8 = (bj & 1) * 8;

    #pragma unroll 1
    for (int it = 0; it < NIT; ++it) {
        if (it + 1 < NIT) {
            ldgA((it + 1) * BK);                 // A prefetch into regs
            loadB((it + 1) & 1, (it + 1) * BK);  // B prefetch into smem
            asm volatile("cp.async.wait_group 1;\n" ::: "memory");
        } else {
            asm volatile("cp.async.wait_group 0;\n" ::: "memory");
        }
        __syncthreads();   // As/Bs stage (it&1) fully visible; prior reads of other buf done
        const __half* Ab = As[it & 1];
        const __half* Bb = Bs[it & 1];

        #pragma unroll
        for (int kk = 0; kk < 2; kk++) {
            const int kc = kk * 16;
            unsigned a[2][4];
            #pragma unroll
            for (int mb = 0; mb < 2; mb++) {
                int mbase = wm * 32 + mb * 16;
                ldm_x4(a[mb][0], a[mb][1], a[mb][2], a[mb][3],
                       Ab + (mbase + a_row) * AST + kc + a_k8);
            }
            unsigned bf[8][2];
            #pragma unroll
            for (int nbp = 0; nbp < 4; nbp++) {
                int nbase = wn * 64 + nbp * 16;
                unsigned r0, r1, r2, r3;
                ldm_x4(r0, r1, r2, r3, Bb + (nbase + b_rowadd) * BST + kc + b_k8);
                bf[nbp * 2][0] = r0;     bf[nbp * 2][1] = r1;
                bf[nbp * 2 + 1][0] = r2; bf[nbp * 2 + 1][1] = r3;
            }
            #pragma unroll
            for (int mb = 0; mb < 2; mb++)
                #pragma unroll
                for (int nb = 0; nb < 8; nb++)
                    mma16816(acc[mb][nb], a[mb], bf[nb]);
        }
        if (it + 1 < NIT) stsA((it + 1) & 1);   // safe: other buffer; ordered by next barrier
        __syncthreads();
    }

    // ---- fused epilogue: tanh + v-dot, reduce over this CTA's 128 k's ----
    const int b = row0 / T_;
    float dp0[8], dp1[8], v0r[8], v1r[8];
    #pragma unroll
    for (int nb = 0; nb < 8; nb++) {
        int col = n0 + wn * 64 + nb * 8 + 2 * tg;
        dp0[nb] = g_dec_proj[b * H_ + col];
        dp1[nb] = g_dec_proj[b * H_ + col + 1];
        v0r[nb] = vvec[col];
        v1r[nb] = vvec[col + 1];
    }
    float rs[4] = {0.f, 0.f, 0.f, 0.f};
    #pragma unroll
    for (int mb = 0; mb < 2; mb++)
        #pragma unroll
        for (int nb = 0; nb < 8; nb++) {
            rs[mb * 2 + 0] += v0r[nb] * tanhf(acc[mb][nb][0] + dp0[nb])
                            + v1r[nb] * tanhf(acc[mb][nb][1] + dp1[nb]);
            rs[mb * 2 + 1] += v0r[nb] * tanhf(acc[mb][nb][2] + dp0[nb])
                            + v1r[nb] * tanhf(acc[mb][nb][3] + dp1[nb]);
        }
    #pragma unroll
    for (int i = 0; i < 4; i++) {
        rs[i] += __shfl_xor_sync(0xffffffffu, rs[i], 1);
        rs[i] += __shfl_xor_sync(0xffffffffu, rs[i], 2);
    }
    if (tg == 0) {
        #pragma unroll
        for (int i = 0; i < 4; i++) {
            int r = wm * 32 + (i >> 1) * 16 + (i & 1) * 8 + g;
            sred[wn * BM + r] = rs[i];
        }
    }
    __syncthreads();
    if (tid < BM)
        g_spart[(size_t)nt * (B_ * T_) + row0 + tid] = sred[tid] + sred[BM + tid];
}

// ---------------- kernel 4: softmax over T per batch ----------------
__global__ void k_softmax(float* __restrict__ attn) {
    __shared__ float s[T_];
    __shared__ float red[8];
    const int b = blockIdx.x, tid = threadIdx.x;
    const int wid = tid >> 5, lane = tid & 31;
    float lmax = -1e30f;
    #pragma unroll
    for (int j = 0; j < 8; j++) {
        int t = tid + j * 256;
        float x = 0.f;
        #pragma unroll
        for (int p = 0; p < 8; p++) x += g_spart[(size_t)p * (B_ * T_) + b * T_ + t];
        s[t] = x;
        lmax = fmaxf(lmax, x);
    }
    #pragma unroll
    for (int o = 16; o > 0; o >>= 1) lmax = fmaxf(lmax, __shfl_xor_sync(~0u, lmax, o));
    if (lane == 0) red[wid] = lmax;
    __syncthreads();
    float smax = red[0];
    #pragma unroll
    for (int k = 1; k < 8; k++) smax = fmaxf(smax, red[k]);
    float lsum = 0.f;
    #pragma unroll
    for (int j = 0; j < 8; j++) lsum += expf(s[tid + j * 256] - smax);
    #pragma unroll
    for (int o = 16; o > 0; o >>= 1) lsum += __shfl_xor_sync(~0u, lsum, o);
    __syncthreads();
    if (lane == 0) red[wid] = lsum;
    __syncthreads();
    float ssum = 0.f;
    #pragma unroll
    for (int k = 0; k < 8; k++) ssum += red[k];
    float inv = 1.f / ssum;
    #pragma unroll
    for (int j = 0; j < 8; j++) {
        int t = tid + j * 256;
        attn[b * T_ + t] = expf(s[t] - smax) * inv;
    }
}

// ---------------- kernel 5: context partials (float2, deterministic t-split) ----------------
__global__ void k_ctx_part(const float* __restrict__ enc, const float* __restrict__ attn) {
    __shared__ float sA[256];
    const int b = blockIdx.x, ec = blockIdx.y, ts = blockIdx.z;
    const int e2 = ec * 512 + threadIdx.x * 2;     // this thread's 2 e-values
    const int t0 = ts * 256;
    sA[threadIdx.x] = attn[b * T_ + t0 + threadIdx.x];
    __syncthreads();
    const float2* base = reinterpret_cast<const float2*>(
        enc + ((size_t)(b * T_ + t0)) * E_ + e2);
    float ax = 0.f, ay = 0.f;
    #pragma unroll 8
    for (int j = 0; j < 256; j++) {
        float2 v = base[(size_t)j * (E_ / 2)];
        float wgt = sA[j];
        ax += wgt * v.x;
        ay += wgt * v.y;
    }
    float* dst = &g_cpart[((size_t)ts * B_ + b) * E_ + e2];
    dst[0] = ax;
    dst[1] = ay;
}

// ---------------- kernel 6: context final sum ----------------
__global__ void k_ctx_sum(float* __restrict__ out) {
    int i = blockIdx.x * 256 + threadIdx.x;
    float x = 0.f;
    #pragma unroll
    for (int ts = 0; ts < 8; ts++) x += g_cpart[(size_t)ts * (B_ * E_) + i];
    out[i] = x;
}

// ---------------- launch ----------------
extern "C" void kernel_launch(void* const* d_in, const int* in_sizes, int n_in,
                              void* d_out, int out_size) {
    const float* dec = (const float*)d_in[0];   // [B,H]
    const float* enc = (const float*)d_in[1];   // [B,T,E]
    const float* W1  = (const float*)d_in[2];   // [H,H]
    const float* W2  = (const float*)d_in[3];   // [H,E]
    const float* v   = (const float*)d_in[4];   // [H]
    float* out = (float*)d_out;                 // context [B,E] then attn [B,T]

    k_w2_convert<<<(H_ * E_) / 1024, 256>>>(W2);
    k_dec_proj<<<H_ / 16, 256>>>(dec, W1);
    k_main<<<(B_ * T_ / BM) * 8, 256>>>(enc, v);
    k_softmax<<<B_, 256>>>(out + B_ * E_);
    dim3 gctx(B_, E_ / 512, 8);
    k_ctx_part<<<gctx, 256>>>(enc, out + B_ * E_);
    k_ctx_sum<<<(B_ * E_) / 256, 256>>>(out);
}

// round 17
// speedup vs baseline: 1.0318x; 1.0064x over previous
#include <cuda_runtime.h>
#include <cuda_fp16.h>
#include <cstdint>
#include <cstddef>

#define B_ 32
#define T_ 2048
#define H_ 1024
#define E_ 1024

// ---------------- device scratch (no allocations allowed) ----------------
__device__ __half g_W2h[H_ * E_];            // W2 fp16, [k][e]
__device__ float  g_dec_proj[B_ * H_];       // [b][k]
__device__ float  g_spart[8 * B_ * T_];      // per-N-tile score partials
__device__ float  g_cpart[8 * B_ * E_];      // per-t-split context partials

// ---------------- helpers ----------------
__device__ __forceinline__ uint32_t smem_u32(const void* p) {
    uint32_t a;
    asm("{ .reg .u64 t; cvta.to.shared.u64 t, %1; cvt.u32.u64 %0, t; }" : "=r"(a) : "l"(p));
    return a;
}
__device__ __forceinline__ void cp16(void* s, const void* g) {
    unsigned sa = smem_u32(s);
    asm volatile("cp.async.cg.shared.global [%0], [%1], 16;\n" :: "r"(sa), "l"(g));
}
__device__ __forceinline__ void ldm_x4(unsigned& r0, unsigned& r1, unsigned& r2, unsigned& r3,
                                       const void* p) {
    unsigned addr = smem_u32(p);
    asm volatile("ldmatrix.sync.aligned.m8n8.x4.shared.b16 {%0,%1,%2,%3}, [%4];\n"
                 : "=r"(r0), "=r"(r1), "=r"(r2), "=r"(r3) : "r"(addr));
}
__device__ __forceinline__ void mma16816(float* c, const unsigned* a, const unsigned* b) {
    asm volatile("mma.sync.aligned.m16n8k16.row.col.f32.f16.f16.f32 "
                 "{%0,%1,%2,%3}, {%4,%5,%6,%7}, {%8,%9}, {%0,%1,%2,%3};\n"
                 : "+f"(c[0]), "+f"(c[1]), "+f"(c[2]), "+f"(c[3])
                 : "r"(a[0]), "r"(a[1]), "r"(a[2]), "r"(a[3]), "r"(b[0]), "r"(b[1]));
}

// ---------------- kernel 1: fused prep (W2 fp32->fp16  +  dec_proj GEMV) ----------------
// blocks [0, 1024): convert W2 chunk;  blocks [1024, 1088): dec_proj n-tile
__global__ void k_prep(const float* __restrict__ W2,
                       const float* __restrict__ dec, const float* __restrict__ W1) {
    __shared__ float sdec[32 * 65];
    __shared__ float sW1[16 * 65];
    const int tid = threadIdx.x;

    if (blockIdx.x < 1024) {
        int i = (blockIdx.x * 256 + tid) * 4;
        float4 f = *reinterpret_cast<const float4*>(W2 + i);
        *reinterpret_cast<__half2*>(&g_W2h[i])     = __floats2half2_rn(f.x, f.y);
        *reinterpret_cast<__half2*>(&g_W2h[i + 2]) = __floats2half2_rn(f.z, f.w);
        return;
    }

    const int n0 = (blockIdx.x - 1024) * 16;
    const int nl = tid & 15, q = tid >> 4;
    float a0 = 0.f, a1 = 0.f;
    for (int h0 = 0; h0 < H_; h0 += 64) {
        __syncthreads();
        #pragma unroll
        for (int j = 0; j < 8; j++) {
            int idx = tid + j * 256;
            int bb = idx >> 6, hh = idx & 63;
            sdec[bb * 65 + hh] = dec[bb * H_ + h0 + hh];
        }
        #pragma unroll
        for (int j = 0; j < 4; j++) {
            int idx = tid + j * 256;
            int nn = idx >> 6, hh = idx & 63;
            sW1[nn * 65 + hh] = W1[(size_t)(n0 + nn) * H_ + h0 + hh];
        }
        __syncthreads();
        #pragma unroll
        for (int h = 0; h < 64; h++) {
            float wv = sW1[nl * 65 + h];
            a0 += sdec[q * 65 + h] * wv;
            a1 += sdec[(q + 16) * 65 + h] * wv;
        }
    }
    g_dec_proj[q * H_ + n0 + nl] = a0;
    g_dec_proj[(q + 16) * H_ + n0 + nl] = a1;
}

// ---------------- kernel 3: fused scores GEMM (R6 schedule, measured-best) ----------------
#define BM 128
#define BN 128
#define BK 32
#define AST 40   // smem row stride in halfs (80B: conflict-free LDSM phases)
#define BST 40
#define NIT (E_ / BK)

__global__ void __launch_bounds__(256, 2)
k_main(const float* __restrict__ enc, const float* __restrict__ vvec) {
    __shared__ __half As[2][BM * AST];
    __shared__ __half Bs[2][BN * BST];
    __shared__ float  sred[2 * BM];

    const int mtile = blockIdx.x >> 3;
    const int nt    = blockIdx.x & 7;
    const int row0  = mtile * BM;
    const int n0    = nt * BN;
    const int tid   = threadIdx.x;
    const int w = tid >> 5, l = tid & 31;
    const int wm = w >> 1, wn = w & 1;
    const int g = l >> 2, tg = l & 3;

    // this thread's two A chunks: chunk c = tid + j*256 -> row c>>2, col (c&3)*8
    const int ar0 = (tid + 0)   >> 2, ac0 = ((tid + 0)   & 3) * 8;
    const int ar1 = (tid + 256) >> 2, ac1 = ((tid + 256) & 3) * 8;

    float4 apre[4];
    auto ldgA = [&](int kc) {
        const float4* p0 = reinterpret_cast<const float4*>(enc + (size_t)(row0 + ar0) * E_ + kc + ac0);
        const float4* p1 = reinterpret_cast<const float4*>(enc + (size_t)(row0 + ar1) * E_ + kc + ac1);
        apre[0] = p0[0]; apre[1] = p0[1];
        apre[2] = p1[0]; apre[3] = p1[1];
    };
    auto stsA = [&](int s) {
        __half2 h[4];
        h[0] = __floats2half2_rn(apre[0].x, apre[0].y);
        h[1] = __floats2half2_rn(apre[0].z, apre[0].w);
        h[2] = __floats2half2_rn(apre[1].x, apre[1].y);
        h[3] = __floats2half2_rn(apre[1].z, apre[1].w);
        *reinterpret_cast<uint4*>(&As[s][ar0 * AST + ac0]) = *reinterpret_cast<uint4*>(h);
        h[0] = __floats2half2_rn(apre[2].x, apre[2].y);
        h[1] = __floats2half2_rn(apre[2].z, apre[2].w);
        h[2] = __floats2half2_rn(apre[3].x, apre[3].y);
        h[3] = __floats2half2_rn(apre[3].z, apre[3].w);
        *reinterpret_cast<uint4*>(&As[s][ar1 * AST + ac1]) = *reinterpret_cast<uint4*>(h);
    };
    auto loadB = [&](int s, int kc) {
        #pragma unroll
        for (int j = 0; j < 2; j++) {
            int c = tid + j * 256;
            int r = c >> 2, cf = c & 3;
            cp16(&Bs[s][r * BST + cf * 8], g_W2h + (size_t)(n0 + r) * E_ + kc + cf * 8);
        }
        asm volatile("cp.async.commit_group;\n" ::: "memory");
    };

    float acc[2][8][4] = {};

    // preamble: stage 0
    ldgA(0);
    loadB(0, 0);
    stsA(0);

    // ldmatrix lane addressing
    const int a_row = l & 15, a_k8 = (l >> 4) * 8;
    const int bj = l >> 3, br = l & 7;
    const int b_rowadd = ((bj >> 1) * 8) + br, b_k8 = (bj & 1) * 8;

    #pragma unroll 1
    for (int it = 0; it < NIT; ++it) {
        if (it + 1 < NIT) {
            ldgA((it + 1) * BK);                 // A prefetch into regs
            loadB((it + 1) & 1, (it + 1) * BK);  // B prefetch into smem
            asm volatile("cp.async.wait_group 1;\n" ::: "memory");
        } else {
            asm volatile("cp.async.wait_group 0;\n" ::: "memory");
        }
        __syncthreads();   // As/Bs stage (it&1) fully visible; prior reads of other buf done
        const __half* Ab = As[it & 1];
        const __half* Bb = Bs[it & 1];

        #pragma unroll
        for (int kk = 0; kk < 2; kk++) {
            const int kc = kk * 16;
            unsigned a[2][4];
            #pragma unroll
            for (int mb = 0; mb < 2; mb++) {
                int mbase = wm * 32 + mb * 16;
                ldm_x4(a[mb][0], a[mb][1], a[mb][2], a[mb][3],
                       Ab + (mbase + a_row) * AST + kc + a_k8);
            }
            unsigned bf[8][2];
            #pragma unroll
            for (int nbp = 0; nbp < 4; nbp++) {
                int nbase = wn * 64 + nbp * 16;
                unsigned r0, r1, r2, r3;
                ldm_x4(r0, r1, r2, r3, Bb + (nbase + b_rowadd) * BST + kc + b_k8);
                bf[nbp * 2][0] = r0;     bf[nbp * 2][1] = r1;
                bf[nbp * 2 + 1][0] = r2; bf[nbp * 2 + 1][1] = r3;
            }
            #pragma unroll
            for (int mb = 0; mb < 2; mb++)
                #pragma unroll
                for (int nb = 0; nb < 8; nb++)
                    mma16816(acc[mb][nb], a[mb], bf[nb]);
        }
        if (it + 1 < NIT) stsA((it + 1) & 1);   // safe: other buffer; ordered by next barrier
        __syncthreads();
    }

    // ---- fused epilogue: tanh + v-dot, reduce over this CTA's 128 k's ----
    const int b = row0 / T_;
    float dp0[8], dp1[8], v0r[8], v1r[8];
    #pragma unroll
    for (int nb = 0; nb < 8; nb++) {
        int col = n0 + wn * 64 + nb * 8 + 2 * tg;
        dp0[nb] = g_dec_proj[b * H_ + col];
        dp1[nb] = g_dec_proj[b * H_ + col + 1];
        v0r[nb] = vvec[col];
        v1r[nb] = vvec[col + 1];
    }
    float rs[4] = {0.f, 0.f, 0.f, 0.f};
    #pragma unroll
    for (int mb = 0; mb < 2; mb++)
        #pragma unroll
        for (int nb = 0; nb < 8; nb++) {
            rs[mb * 2 + 0] += v0r[nb] * tanhf(acc[mb][nb][0] + dp0[nb])
                            + v1r[nb] * tanhf(acc[mb][nb][1] + dp1[nb]);
            rs[mb * 2 + 1] += v0r[nb] * tanhf(acc[mb][nb][2] + dp0[nb])
                            + v1r[nb] * tanhf(acc[mb][nb][3] + dp1[nb]);
        }
    #pragma unroll
    for (int i = 0; i < 4; i++) {
        rs[i] += __shfl_xor_sync(0xffffffffu, rs[i], 1);
        rs[i] += __shfl_xor_sync(0xffffffffu, rs[i], 2);
    }
    if (tg == 0) {
        #pragma unroll
        for (int i = 0; i < 4; i++) {
            int r = wm * 32 + (i >> 1) * 16 + (i & 1) * 8 + g;
            sred[wn * BM + r] = rs[i];
        }
    }
    __syncthreads();
    if (tid < BM)
        g_spart[(size_t)nt * (B_ * T_) + row0 + tid] = sred[tid] + sred[BM + tid];
}

// ---------------- kernel 4: softmax over T per batch (512 threads) ----------------
__global__ void k_softmax(float* __restrict__ attn) {
    __shared__ float s[T_];
    __shared__ float red[16];
    const int b = blockIdx.x, tid = threadIdx.x;
    const int wid = tid >> 5, lane = tid & 31;
    float lmax = -1e30f;
    #pragma unroll
    for (int j = 0; j < 4; j++) {
        int t = tid + j * 512;
        float x = 0.f;
        #pragma unroll
        for (int p = 0; p < 8; p++) x += g_spart[(size_t)p * (B_ * T_) + b * T_ + t];
        s[t] = x;
        lmax = fmaxf(lmax, x);
    }
    #pragma unroll
    for (int o = 16; o > 0; o >>= 1) lmax = fmaxf(lmax, __shfl_xor_sync(~0u, lmax, o));
    if (lane == 0) red[wid] = lmax;
    __syncthreads();
    float smax = red[0];
    #pragma unroll
    for (int k = 1; k < 16; k++) smax = fmaxf(smax, red[k]);
    float lsum = 0.f;
    #pragma unroll
    for (int j = 0; j < 4; j++) lsum += expf(s[tid + j * 512] - smax);
    #pragma unroll
    for (int o = 16; o > 0; o >>= 1) lsum += __shfl_xor_sync(~0u, lsum, o);
    __syncthreads();
    if (lane == 0) red[wid] = lsum;
    __syncthreads();
    float ssum = 0.f;
    #pragma unroll
    for (int k = 0; k < 16; k++) ssum += red[k];
    float inv = 1.f / ssum;
    #pragma unroll
    for (int j = 0; j < 4; j++) {
        int t = tid + j * 512;
        attn[b * T_ + t] = expf(s[t] - smax) * inv;
    }
}

// ---------------- kernel 5: context partials (float2, deterministic t-split) ----------------
__global__ void k_ctx_part(const float* __restrict__ enc, const float* __restrict__ attn) {
    __shared__ float sA[256];
    const int b = blockIdx.x, ec = blockIdx.y, ts = blockIdx.z;
    const int e2 = ec * 512 + threadIdx.x * 2;     // this thread's 2 e-values
    const int t0 = ts * 256;
    sA[threadIdx.x] = attn[b * T_ + t0 + threadIdx.x];
    __syncthreads();
    const float2* base = reinterpret_cast<const float2*>(
        enc + ((size_t)(b * T_ + t0)) * E_ + e2);
    float ax = 0.f, ay = 0.f;
    #pragma unroll 8
    for (int j = 0; j < 256; j++) {
        float2 v = base[(size_t)j * (E_ / 2)];
        float wgt = sA[j];
        ax += wgt * v.x;
        ay += wgt * v.y;
    }
    float* dst = &g_cpart[((size_t)ts * B_ + b) * E_ + e2];
    dst[0] = ax;
    dst[1] = ay;
}

// ---------------- kernel 6: context final sum ----------------
__global__ void k_ctx_sum(float* __restrict__ out) {
    int i = blockIdx.x * 256 + threadIdx.x;
    float x = 0.f;
    #pragma unroll
    for (int ts = 0; ts < 8; ts++) x += g_cpart[(size_t)ts * (B_ * E_) + i];
    out[i] = x;
}

// ---------------- launch ----------------
extern "C" void kernel_launch(void* const* d_in, const int* in_sizes, int n_in,
                              void* d_out, int out_size) {
    const float* dec = (const float*)d_in[0];   // [B,H]
    const float* enc = (const float*)d_in[1];   // [B,T,E]
    const float* W1  = (const float*)d_in[2];   // [H,H]
    const float* W2  = (const float*)d_in[3];   // [H,E]
    const float* v   = (const float*)d_in[4];   // [H]
    float* out = (float*)d_out;                 // context [B,E] then attn [B,T]

    k_prep<<<1024 + H_ / 16, 256>>>(W2, dec, W1);
    k_main<<<(B_ * T_ / BM) * 8, 256>>>(enc, v);
    k_softmax<<<B_, 512>>>(out + B_ * E_);
    dim3 gctx(B_, E_ / 512, 8);
    k_ctx_part<<<gctx, 256>>>(enc, out + B_ * E_);
    k_ctx_sum<<<(B_ * E_) / 256, 256>>>(out);
}